// round 4
// baseline (speedup 1.0000x reference)
#include <cuda_runtime.h>
#include <cuda_bf16.h>
#include <cuda_fp8.h>
#include <math.h>
#include <stdint.h>

#define D 512
#define Bsz 16
#define L 2048
#define HID 2048
#define GH 128
#define NTOK (Bsz * L)   // 32768

typedef uint8_t fp8_t;

// ------------------------- scratch (static device globals) -------------------------
__device__ fp8_t         g_h[(size_t)NTOK * D];    // ln1/ln2 out (fp8 GEMM A)
__device__ fp8_t         g_gm[(size_t)NTOK * D];   // gelu(conv mix) fp8
__device__ __nv_bfloat16 g_m2[(size_t)NTOK * D];   // mixed2 bf16
__device__ fp8_t         g_a2[(size_t)NTOK * D];   // m2*gate fp8
__device__ float         g_x1[(size_t)NTOK * D];   // first residual out fp32
__device__ fp8_t         g_t[(size_t)NTOK * HID];  // ffn hidden fp8
__device__ fp8_t g_wmixB[D * D];                   // wmix as [o,c]
__device__ fp8_t g_woutT[D * D];                   // wout^T  [n,k]
__device__ fp8_t g_w1T[HID * D];                   // ffn_w1^T [hid,d]
__device__ fp8_t g_w2T[D * HID];                   // ffn_w2^T [d,hid]
__device__ float g_part[Bsz * 16 * D];
__device__ float g_gate[Bsz * D];
__device__ float g_taps[D * 7];
__device__ float g_cbias[D];

__device__ __forceinline__ float gelu_exact(float v) {
    return 0.5f * v * (1.0f + erff(v * 0.70710678118654752f));
}
__device__ __forceinline__ fp8_t f2fp8(float v) {
    return (fp8_t)__nv_cvt_float_to_fp8(v, __NV_SATFINITE, __NV_E4M3);
}
__device__ __forceinline__ float fp82f(fp8_t v) {
    __half_raw hr = __nv_cvt_fp8_to_halfraw(v, __NV_E4M3);
    return __half2float(*reinterpret_cast<__half*>(&hr));
}

__device__ __forceinline__ uint32_t smem_u32(const void* p) {
    uint32_t a;
    asm("{ .reg .u64 t; cvta.to.shared.u64 t, %1; cvt.u32.u64 %0, t; }" : "=r"(a) : "l"(p));
    return a;
}
__device__ __forceinline__ void cpasync16(uint32_t s, const void* g) {
    asm volatile("cp.async.cg.shared.global [%0], [%1], 16;" :: "r"(s), "l"(g));
}
__device__ __forceinline__ void cp_commit() { asm volatile("cp.async.commit_group;"); }
template <int N>
__device__ __forceinline__ void cp_wait() {
    asm volatile("cp.async.wait_group %0;" :: "n"(N));
}
__device__ __forceinline__ void ldmat4(uint32_t* r, uint32_t addr) {
    asm volatile("ldmatrix.sync.aligned.m8n8.x4.shared.b16 {%0,%1,%2,%3}, [%4];"
                 : "=r"(r[0]), "=r"(r[1]), "=r"(r[2]), "=r"(r[3]) : "r"(addr));
}
// fp8 e4m3 MMA, m16n8k32, fp32 accumulate
__device__ __forceinline__ void mma_fp8(float* c, const uint32_t* a, uint32_t b0,
                                        uint32_t b1) {
    asm volatile(
        "mma.sync.aligned.m16n8k32.row.col.f32.e4m3.e4m3.f32 "
        "{%0,%1,%2,%3}, {%4,%5,%6,%7}, {%8,%9}, {%0,%1,%2,%3};"
        : "+f"(c[0]), "+f"(c[1]), "+f"(c[2]), "+f"(c[3])
        : "r"(a[0]), "r"(a[1]), "r"(a[2]), "r"(a[3]), "r"(b0), "r"(b1));
}

// ------------------------- LayerNorm (fp32 in -> fp8 out) --------------------------
__global__ void ln_kernel(const float* __restrict__ x, const float* __restrict__ g,
                          const float* __restrict__ bb, fp8_t* __restrict__ out) {
    int n = blockIdx.x;
    const float* xr = x + (size_t)n * D;
    int t = threadIdx.x;
    float v[4];
    float s = 0.f;
#pragma unroll
    for (int i = 0; i < 4; i++) { v[i] = xr[t + 128 * i]; s += v[i]; }
    __shared__ float red[4];
#pragma unroll
    for (int o = 16; o; o >>= 1) s += __shfl_xor_sync(~0u, s, o);
    if ((t & 31) == 0) red[t >> 5] = s;
    __syncthreads();
    float mean = (red[0] + red[1] + red[2] + red[3]) * (1.f / 512.f);
    float s2 = 0.f;
#pragma unroll
    for (int i = 0; i < 4; i++) { float dd = v[i] - mean; s2 += dd * dd; }
#pragma unroll
    for (int o = 16; o; o >>= 1) s2 += __shfl_xor_sync(~0u, s2, o);
    __syncthreads();
    if ((t & 31) == 0) red[t >> 5] = s2;
    __syncthreads();
    float rstd = rsqrtf((red[0] + red[1] + red[2] + red[3]) * (1.f / 512.f) + 1e-5f);
    fp8_t* orow = out + (size_t)n * D;
#pragma unroll
    for (int i = 0; i < 4; i++) {
        int d = t + 128 * i;
        orow[d] = f2fp8((v[i] - mean) * rstd * g[d] + bb[d]);
    }
}

// ------------------------- combine dwconv taps -------------------------
__global__ void taps_kernel(const float* __restrict__ w3, const float* __restrict__ b3,
                            const float* __restrict__ w5, const float* __restrict__ b5,
                            const float* __restrict__ w7, const float* __restrict__ b7) {
    int d = threadIdx.x;
#pragma unroll
    for (int j = 0; j < 7; j++) {
        float tv = w7[d * 7 + j];
        if (j >= 1 && j <= 5) tv += w5[d * 5 + (j - 1)];
        if (j >= 2 && j <= 4) tv += w3[d * 3 + (j - 2)];
        g_taps[d * 7 + j] = tv * (1.f / 3.f);
    }
    g_cbias[d] = (b3[d] + b5[d] + b7[d]) * (1.f / 3.f);
}

// ------------------------- conv (7-tap) + exact GELU, fp8 in/out -------------------
__global__ void conv_kernel(const fp8_t* __restrict__ h, fp8_t* __restrict__ out) {
    int idx = blockIdx.x * 256 + threadIdx.x;
    int d = idx & (D - 1);
    int n = idx >> 9;
    int l = n & (L - 1);
    float acc = g_cbias[d];
#pragma unroll
    for (int j = 0; j < 7; j++) {
        int lp = l + j - 3;
        if (lp >= 0 && lp < L)
            acc = fmaf(fp82f(h[(size_t)(n + (j - 3)) * D + d]), g_taps[d * 7 + j], acc);
    }
    out[idx] = f2fp8(gelu_exact(acc));
}

// ------------------------- weight transpose+convert / convert ----------------------
__global__ void transconv_kernel(const float* __restrict__ in, fp8_t* __restrict__ outp,
                                 int R, int C) {
    __shared__ float tile[32][33];
    int x = blockIdx.x * 32 + threadIdx.x;
    int y = blockIdx.y * 32 + threadIdx.y;
#pragma unroll
    for (int i = 0; i < 32; i += 8)
        tile[threadIdx.y + i][threadIdx.x] = in[(size_t)(y + i) * C + x];
    __syncthreads();
    int ox = blockIdx.y * 32 + threadIdx.x;
    int oy = blockIdx.x * 32 + threadIdx.y;
#pragma unroll
    for (int i = 0; i < 32; i += 8)
        outp[(size_t)(oy + i) * R + ox] = f2fp8(tile[threadIdx.x][threadIdx.y + i]);
}
__global__ void convert_kernel(const float* __restrict__ in, fp8_t* __restrict__ o) {
    int idx = blockIdx.x * 256 + threadIdx.x;
    o[idx] = f2fp8(in[idx]);
}

// ------------------------- partial column sums over L ------------------------------
__global__ void colsum_kernel(const __nv_bfloat16* __restrict__ m2) {
    int b = blockIdx.y, chunk = blockIdx.x;
    int d = threadIdx.x;
    const __nv_bfloat16* base = m2 + ((size_t)(b * L + chunk * 128)) * D + d;
    float s = 0.f;
#pragma unroll 4
    for (int l = 0; l < 128; l++) s += __bfloat162float(base[(size_t)l * D]);
    g_part[(b * 16 + chunk) * D + d] = s;
}

// ------------------------- gate MLP (tiny) ------------------------------------------
__global__ void gate_kernel(const float* __restrict__ cg_w1, const float* __restrict__ cg_b1,
                            const float* __restrict__ cg_w2, const float* __restrict__ cg_b2) {
    int b = blockIdx.x;
    int t = threadIdx.x;
    __shared__ float ct[D];
    __shared__ float hid[GH];
    for (int d = t; d < D; d += 128) {
        float s = 0.f;
#pragma unroll
        for (int c = 0; c < 16; c++) s += g_part[(b * 16 + c) * D + d];
        ct[d] = s * (1.f / (float)L);
    }
    __syncthreads();
    {
        float hv = cg_b1[t];
        for (int d = 0; d < D; d++) hv = fmaf(ct[d], cg_w1[d * GH + t], hv);
        hid[t] = gelu_exact(hv);
    }
    __syncthreads();
    for (int o = t; o < D; o += 128) {
        float s = cg_b2[o];
#pragma unroll 4
        for (int j = 0; j < GH; j++) s = fmaf(hid[j], cg_w2[j * D + o], s);
        g_gate[b * D + o] = 1.f / (1.f + expf(-s));
    }
}

// ------------------------- gate multiply -> fp8 A for GEMM2 ------------------------
__global__ void gatemul_kernel(const __nv_bfloat16* __restrict__ m2,
                               fp8_t* __restrict__ a2) {
    int idx = blockIdx.x * 256 + threadIdx.x;
    int d = idx & (D - 1);
    int b = idx >> 20;
    a2[idx] = f2fp8(__bfloat162float(m2[idx]) * g_gate[b * D + d]);
}

// ------------------------- FP8 MMA GEMM 128x128x64, cp.async double buffer ---------
// C = epi(A[M,K] @ Bw[N,K]^T + bias)
// epi 0: bf16 +bias ; epi 1: fp8 gelu(+bias) ; epi 2: fp32 res + (+bias)*scale
#define ROWB 80                     // smem bytes per 64-fp8 row (+16B pad)
#define TILEB (128 * ROWB)          // 10240 bytes per tile
#define STAGEB (2 * TILEB)          // A+B per stage

__global__ __launch_bounds__(256) void fgemm_kernel(
    const fp8_t* __restrict__ A, const fp8_t* __restrict__ Bw,
    const float* __restrict__ bias, float* __restrict__ Cf,
    __nv_bfloat16* __restrict__ Cbf, fp8_t* __restrict__ C8, int M, int Nn, int K,
    int epi, const float* __restrict__ res, const float* __restrict__ scale) {
    __shared__ __align__(16) char smem[2 * STAGEB];

    const int tid = threadIdx.x;
    const int bm = blockIdx.y << 7;
    const int bn = blockIdx.x << 7;
    const uint32_t sbase = smem_u32(smem);

    const int lrow = tid >> 2;       // 0..63 (x2 rounds -> 128 rows)
    const int lc = tid & 3;          // 16B chunk within 64B row

    auto load_stage = [&](int s, int k0) {
        uint32_t st = sbase + s * STAGEB;
#pragma unroll
        for (int i = 0; i < 2; i++) {
            int row = lrow + i * 64;
            uint32_t off = row * ROWB + lc * 16;
            cpasync16(st + off, A + (size_t)(bm + row) * K + k0 + lc * 16);
            cpasync16(st + TILEB + off, Bw + (size_t)(bn + row) * K + k0 + lc * 16);
        }
    };

    const int wid = tid >> 5, lane = tid & 31;
    const int wm = wid & 3;          // 4 warps over M: 32 rows each
    const int wn = wid >> 2;         // 2 warps over N: 64 cols each

    float acc[2][8][4];
#pragma unroll
    for (int mt = 0; mt < 2; mt++)
#pragma unroll
        for (int nt = 0; nt < 8; nt++)
#pragma unroll
            for (int r = 0; r < 4; r++) acc[mt][nt][r] = 0.f;

    const int KT = K >> 6;
    load_stage(0, 0);
    cp_commit();

    // ldmatrix source offsets (within stage); fragment = 4 consecutive bytes/thread
    const uint32_t a_off = (wm * 32 + (lane & 15)) * ROWB + (lane >> 4) * 16;
    const uint32_t b_off = TILEB + (wn * 64 + (lane >> 4) * 8 + (lane & 7)) * ROWB +
                           ((lane >> 3) & 1) * 16;

    for (int kt = 0; kt < KT; kt++) {
        int s = kt & 1;
        if (kt + 1 < KT) {
            load_stage(s ^ 1, (kt + 1) << 6);
            cp_commit();
            cp_wait<1>();
        } else {
            cp_wait<0>();
        }
        __syncthreads();
        uint32_t st = sbase + s * STAGEB;
#pragma unroll
        for (int kk = 0; kk < 2; kk++) {   // two k32 steps per 64B chunk
            uint32_t a[2][4], b[4][4];
#pragma unroll
            for (int mt = 0; mt < 2; mt++)
                ldmat4(a[mt], st + a_off + mt * 16 * ROWB + kk * 32);
#pragma unroll
            for (int i = 0; i < 4; i++)
                ldmat4(b[i], st + b_off + i * 16 * ROWB + kk * 32);
#pragma unroll
            for (int mt = 0; mt < 2; mt++)
#pragma unroll
                for (int nt = 0; nt < 8; nt++)
                    mma_fp8(acc[mt][nt], a[mt], b[nt >> 1][(nt & 1) * 2],
                            b[nt >> 1][(nt & 1) * 2 + 1]);
        }
        __syncthreads();
    }

    // ---- epilogue ----
    const int qrow = lane >> 2;
    const int qcol = (lane & 3) * 2;
#pragma unroll
    for (int mt = 0; mt < 2; mt++) {
#pragma unroll
        for (int nt = 0; nt < 8; nt++) {
            int col = bn + wn * 64 + nt * 8 + qcol;
            float2 bi = *reinterpret_cast<const float2*>(bias + col);
            float2 sc = make_float2(0.f, 0.f);
            if (epi == 2) sc = *reinterpret_cast<const float2*>(scale + col);
#pragma unroll
            for (int half = 0; half < 2; half++) {
                int row = bm + wm * 32 + mt * 16 + qrow + half * 8;
                size_t off = (size_t)row * Nn + col;
                float v0 = acc[mt][nt][half * 2 + 0] + bi.x;
                float v1 = acc[mt][nt][half * 2 + 1] + bi.y;
                if (epi == 0) {
                    __nv_bfloat162 o;
                    o.x = __float2bfloat16(v0);
                    o.y = __float2bfloat16(v1);
                    *reinterpret_cast<__nv_bfloat162*>(Cbf + off) = o;
                } else if (epi == 1) {
                    uint16_t pk = (uint16_t)f2fp8(gelu_exact(v0)) |
                                  ((uint16_t)f2fp8(gelu_exact(v1)) << 8);
                    *reinterpret_cast<uint16_t*>(C8 + off) = pk;
                } else {
                    float2 rv = *reinterpret_cast<const float2*>(res + off);
                    *reinterpret_cast<float2*>(Cf + off) =
                        make_float2(rv.x + v0 * sc.x, rv.y + v1 * sc.y);
                }
            }
        }
    }
}

// ------------------------- host launch ---------------------------------------------
extern "C" void kernel_launch(void* const* d_in, const int* in_sizes, int n_in,
                              void* d_out, int out_size) {
    const float* x      = (const float*)d_in[0];
    const float* ln1_g  = (const float*)d_in[1];
    const float* ln1_b  = (const float*)d_in[2];
    const float* w3     = (const float*)d_in[3];
    const float* b3     = (const float*)d_in[4];
    const float* w5     = (const float*)d_in[5];
    const float* b5     = (const float*)d_in[6];
    const float* w7     = (const float*)d_in[7];
    const float* b7     = (const float*)d_in[8];
    const float* wmix   = (const float*)d_in[9];
    const float* bmix   = (const float*)d_in[10];
    const float* cg_w1  = (const float*)d_in[11];
    const float* cg_b1  = (const float*)d_in[12];
    const float* cg_w2  = (const float*)d_in[13];
    const float* cg_b2  = (const float*)d_in[14];
    const float* wout   = (const float*)d_in[15];
    const float* bout   = (const float*)d_in[16];
    const float* ls1    = (const float*)d_in[17];
    const float* ln2_g  = (const float*)d_in[18];
    const float* ln2_b  = (const float*)d_in[19];
    const float* ffn_w1 = (const float*)d_in[20];
    const float* ffn_b1 = (const float*)d_in[21];
    const float* ffn_w2 = (const float*)d_in[22];
    const float* ffn_b2 = (const float*)d_in[23];
    const float* ls2    = (const float*)d_in[24];
    float* out = (float*)d_out;

    void* p;
    cudaGetSymbolAddress(&p, g_h);     fp8_t* hbuf  = (fp8_t*)p;
    cudaGetSymbolAddress(&p, g_gm);    fp8_t* gmbuf = (fp8_t*)p;
    cudaGetSymbolAddress(&p, g_m2);    __nv_bfloat16* m2buf = (__nv_bfloat16*)p;
    cudaGetSymbolAddress(&p, g_a2);    fp8_t* a2buf = (fp8_t*)p;
    cudaGetSymbolAddress(&p, g_x1);    float* x1buf = (float*)p;
    cudaGetSymbolAddress(&p, g_t);     fp8_t* tbuf  = (fp8_t*)p;
    cudaGetSymbolAddress(&p, g_wmixB); fp8_t* wmixB = (fp8_t*)p;
    cudaGetSymbolAddress(&p, g_woutT); fp8_t* woutT = (fp8_t*)p;
    cudaGetSymbolAddress(&p, g_w1T);   fp8_t* w1T   = (fp8_t*)p;
    cudaGetSymbolAddress(&p, g_w2T);   fp8_t* w2T   = (fp8_t*)p;

    // weight prep
    convert_kernel<<<(D * D) / 256, 256>>>(wmix, wmixB);
    transconv_kernel<<<dim3(D / 32, D / 32), dim3(32, 8)>>>(wout, woutT, D, D);
    transconv_kernel<<<dim3(HID / 32, D / 32), dim3(32, 8)>>>(ffn_w1, w1T, D, HID);
    transconv_kernel<<<dim3(D / 32, HID / 32), dim3(32, 8)>>>(ffn_w2, w2T, HID, D);
    taps_kernel<<<1, 512>>>(w3, b3, w5, b5, w7, b7);

    // 1. LN1 -> fp8
    ln_kernel<<<NTOK, 128>>>(x, ln1_g, ln1_b, hbuf);
    // 2. conv + gelu -> fp8
    conv_kernel<<<(NTOK * D) / 256, 256>>>(hbuf, gmbuf);
    // 3. mixed2 = gelu(conv) @ wmix^T + bmix   (bf16 out)
    fgemm_kernel<<<dim3(D / 128, NTOK / 128), 256>>>(
        gmbuf, wmixB, bmix, nullptr, m2buf, nullptr, NTOK, D, D, 0, nullptr, nullptr);
    // 4. channel token partial sums + gate MLP
    colsum_kernel<<<dim3(16, Bsz), 512>>>(m2buf);
    gate_kernel<<<Bsz, 128>>>(cg_w1, cg_b1, cg_w2, cg_b2);
    // 5. a2 = fp8(m2 * gate)
    gatemul_kernel<<<(NTOK * D) / 256, 256>>>(m2buf, a2buf);
    // 6. x1 = x + (a2 @ wout + bout) * ls1
    fgemm_kernel<<<dim3(D / 128, NTOK / 128), 256>>>(
        a2buf, woutT, bout, x1buf, nullptr, nullptr, NTOK, D, D, 2, x, ls1);
    // 7. LN2 -> fp8
    ln_kernel<<<NTOK, 128>>>(x1buf, ln2_g, ln2_b, hbuf);
    // 8. t = gelu(h2 @ ffn_w1 + b1)  (fp8 out)
    fgemm_kernel<<<dim3(HID / 128, NTOK / 128), 256>>>(
        hbuf, w1T, ffn_b1, nullptr, nullptr, tbuf, NTOK, HID, D, 1, nullptr, nullptr);
    // 9. out = x1 + (t @ ffn_w2 + b2) * ls2
    fgemm_kernel<<<dim3(D / 128, NTOK / 128), 256>>>(
        tbuf, w2T, ffn_b2, out, nullptr, nullptr, NTOK, D, HID, 2, x1buf, ls2);
}

// round 5
// speedup vs baseline: 1.2091x; 1.2091x over previous
#include <cuda_runtime.h>
#include <cuda_bf16.h>
#include <math.h>
#include <stdint.h>

#define D 512
#define Bsz 16
#define L 2048
#define HID 2048
#define GH 128
#define NTOK (Bsz * L)   // 32768

typedef __nv_bfloat16 bf16;
typedef __nv_bfloat162 bf162;

// ------------------------- scratch (static device globals) -------------------------
__device__ bf16  g_h[(size_t)NTOK * D];    // ln1/ln2 out
__device__ bf16  g_gm[(size_t)NTOK * D];   // gelu(conv mix)
__device__ bf16  g_m2[(size_t)NTOK * D];   // mixed2
__device__ float g_x1[(size_t)NTOK * D];   // first residual out
__device__ bf16  g_t[(size_t)NTOK * HID];  // ffn hidden
__device__ bf16  g_wmixB[D * D];
__device__ bf16  g_woutT[D * D];
__device__ bf16  g_w1T[HID * D];
__device__ bf16  g_w2T[D * HID];
__device__ float g_ct[Bsz * D];            // column sums (atomic)
__device__ float g_gate[Bsz * D];
__device__ float g_taps[D * 7];
__device__ float g_cbias[D];

__device__ __forceinline__ float gelu_exact(float v) {
    return 0.5f * v * (1.0f + erff(v * 0.70710678118654752f));
}
__device__ __forceinline__ uint32_t smem_u32(const void* p) {
    uint32_t a;
    asm("{ .reg .u64 t; cvta.to.shared.u64 t, %1; cvt.u32.u64 %0, t; }" : "=r"(a) : "l"(p));
    return a;
}
__device__ __forceinline__ void cpasync16(uint32_t s, const void* g) {
    asm volatile("cp.async.cg.shared.global [%0], [%1], 16;" :: "r"(s), "l"(g));
}
__device__ __forceinline__ void cp_commit() { asm volatile("cp.async.commit_group;"); }
template <int N>
__device__ __forceinline__ void cp_wait() {
    asm volatile("cp.async.wait_group %0;" :: "n"(N));
}
__device__ __forceinline__ void ldmat4(uint32_t* r, uint32_t addr) {
    asm volatile("ldmatrix.sync.aligned.m8n8.x4.shared.b16 {%0,%1,%2,%3}, [%4];"
                 : "=r"(r[0]), "=r"(r[1]), "=r"(r[2]), "=r"(r[3]) : "r"(addr));
}
__device__ __forceinline__ void mma16816(float* c, const uint32_t* a, uint32_t b0,
                                         uint32_t b1) {
    asm volatile(
        "mma.sync.aligned.m16n8k16.row.col.f32.bf16.bf16.f32 "
        "{%0,%1,%2,%3}, {%4,%5,%6,%7}, {%8,%9}, {%0,%1,%2,%3};"
        : "+f"(c[0]), "+f"(c[1]), "+f"(c[2]), "+f"(c[3])
        : "r"(a[0]), "r"(a[1]), "r"(a[2]), "r"(a[3]), "r"(b0), "r"(b1));
}
__device__ __forceinline__ uint32_t mulbf2(uint32_t x, bf162 g) {
    bf162 v = *reinterpret_cast<bf162*>(&x);
    v = __hmul2(v, g);
    return *reinterpret_cast<uint32_t*>(&v);
}

// ------------------------- LayerNorm (fp32 in -> bf16 out), float4 ------------------
__global__ void ln_kernel(const float* __restrict__ x, const float* __restrict__ g,
                          const float* __restrict__ bb, bf16* __restrict__ out) {
    int n = blockIdx.x;
    const float* xr = x + (size_t)n * D;
    int t = threadIdx.x;
    float4 v = *reinterpret_cast<const float4*>(xr + t * 4);
    float s = v.x + v.y + v.z + v.w;
    __shared__ float red[4];
#pragma unroll
    for (int o = 16; o; o >>= 1) s += __shfl_xor_sync(~0u, s, o);
    if ((t & 31) == 0) red[t >> 5] = s;
    __syncthreads();
    float mean = (red[0] + red[1] + red[2] + red[3]) * (1.f / 512.f);
    float dx = v.x - mean, dy = v.y - mean, dz = v.z - mean, dw = v.w - mean;
    float s2 = dx * dx + dy * dy + dz * dz + dw * dw;
#pragma unroll
    for (int o = 16; o; o >>= 1) s2 += __shfl_xor_sync(~0u, s2, o);
    __syncthreads();
    if ((t & 31) == 0) red[t >> 5] = s2;
    __syncthreads();
    float rstd = rsqrtf((red[0] + red[1] + red[2] + red[3]) * (1.f / 512.f) + 1e-5f);
    float4 gg = *reinterpret_cast<const float4*>(g + t * 4);
    float4 bbv = *reinterpret_cast<const float4*>(bb + t * 4);
    bf162 o1, o2;
    o1.x = __float2bfloat16(dx * rstd * gg.x + bbv.x);
    o1.y = __float2bfloat16(dy * rstd * gg.y + bbv.y);
    o2.x = __float2bfloat16(dz * rstd * gg.z + bbv.z);
    o2.y = __float2bfloat16(dw * rstd * gg.w + bbv.w);
    uint2 pk;
    pk.x = *reinterpret_cast<uint32_t*>(&o1);
    pk.y = *reinterpret_cast<uint32_t*>(&o2);
    *reinterpret_cast<uint2*>(out + (size_t)n * D + t * 4) = pk;
}

// ------------------------- combine dwconv taps -------------------------
__global__ void taps_kernel(const float* __restrict__ w3, const float* __restrict__ b3,
                            const float* __restrict__ w5, const float* __restrict__ b5,
                            const float* __restrict__ w7, const float* __restrict__ b7) {
    int d = threadIdx.x;
#pragma unroll
    for (int j = 0; j < 7; j++) {
        float tv = w7[d * 7 + j];
        if (j >= 1 && j <= 5) tv += w5[d * 5 + (j - 1)];
        if (j >= 2 && j <= 4) tv += w3[d * 3 + (j - 2)];
        g_taps[d * 7 + j] = tv * (1.f / 3.f);
    }
    g_cbias[d] = (b3[d] + b5[d] + b7[d]) * (1.f / 3.f);
}

// ------------------------- conv (7-tap) + exact GELU, bf16x2 -----------------------
__global__ void conv_kernel(const bf16* __restrict__ h, bf16* __restrict__ out) {
    int idx = blockIdx.x * 256 + threadIdx.x;  // over NTOK * 256 (pairs)
    int d = (idx & 255) * 2;
    int n = idx >> 8;
    int l = n & (L - 1);
    float ax = g_cbias[d], ay = g_cbias[d + 1];
#pragma unroll
    for (int j = 0; j < 7; j++) {
        int lp = l + j - 3;
        if (lp >= 0 && lp < L) {
            bf162 hv = *reinterpret_cast<const bf162*>(h + (size_t)(n + (j - 3)) * D + d);
            ax = fmaf(__bfloat162float(hv.x), g_taps[d * 7 + j], ax);
            ay = fmaf(__bfloat162float(hv.y), g_taps[(d + 1) * 7 + j], ay);
        }
    }
    bf162 o;
    o.x = __float2bfloat16(gelu_exact(ax));
    o.y = __float2bfloat16(gelu_exact(ay));
    *reinterpret_cast<bf162*>(out + (size_t)n * D + d) = o;
}

// ------------------------- weight transpose+convert / convert ----------------------
__global__ void transconv_kernel(const float* __restrict__ in, bf16* __restrict__ outp,
                                 int R, int C) {
    __shared__ float tile[32][33];
    int x = blockIdx.x * 32 + threadIdx.x;
    int y = blockIdx.y * 32 + threadIdx.y;
#pragma unroll
    for (int i = 0; i < 32; i += 8)
        tile[threadIdx.y + i][threadIdx.x] = in[(size_t)(y + i) * C + x];
    __syncthreads();
    int ox = blockIdx.y * 32 + threadIdx.x;
    int oy = blockIdx.x * 32 + threadIdx.y;
#pragma unroll
    for (int i = 0; i < 32; i += 8)
        outp[(size_t)(oy + i) * R + ox] = __float2bfloat16(tile[threadIdx.x][threadIdx.y + i]);
}
__global__ void convert_kernel(const float* __restrict__ in, bf16* __restrict__ o) {
    int idx = blockIdx.x * 256 + threadIdx.x;
    o[idx] = __float2bfloat16(in[idx]);
}
__global__ void zero_ct_kernel() {
    g_ct[blockIdx.x * 256 + threadIdx.x] = 0.f;
}

// ------------------------- gate MLP (tiny) ------------------------------------------
__global__ void gate_kernel(const float* __restrict__ cg_w1, const float* __restrict__ cg_b1,
                            const float* __restrict__ cg_w2, const float* __restrict__ cg_b2,
                            const float* __restrict__ bmix) {
    int b = blockIdx.x;
    int t = threadIdx.x;
    __shared__ float ct[D];
    __shared__ float hid[GH];
    for (int d = t; d < D; d += 128)
        ct[d] = g_ct[b * D + d] * (1.f / (float)L) + bmix[d];
    __syncthreads();
    {
        float hv = cg_b1[t];
        for (int d = 0; d < D; d++) hv = fmaf(ct[d], cg_w1[d * GH + t], hv);
        hid[t] = gelu_exact(hv);
    }
    __syncthreads();
    for (int o = t; o < D; o += 128) {
        float s = cg_b2[o];
#pragma unroll 4
        for (int j = 0; j < GH; j++) s = fmaf(hid[j], cg_w2[j * D + o], s);
        g_gate[b * D + o] = 1.f / (1.f + expf(-s));
    }
}

// ------------------------- bf16 MMA GEMM 128x128x64, warp tile 64x64 ---------------
// C = epi(A[M,K] (optionally * gate along K) @ Bw[N,K]^T + bias)
// epi 0: bf16 +bias, accumulate column sums into g_ct (gemm1)
// epi 1: bf16 gelu(+bias)                              (gemm3)
// epi 2: fp32 res + (+bias)*scale                      (gemm2/4)
#define ROWB 144                     // 128B data + 16B pad
#define TILEB (128 * ROWB)           // 18432
#define STAGEB (2 * TILEB)           // A+B per stage
#define SMEMB (2 * STAGEB)           // 73728

__global__ __launch_bounds__(128) void hgemm_kernel(
    const bf16* __restrict__ A, const bf16* __restrict__ Bw,
    const float* __restrict__ bias, float* __restrict__ Cf, bf16* __restrict__ Cb,
    int M, int Nn, int K, int epi, const float* __restrict__ res,
    const float* __restrict__ scale, const float* __restrict__ gate) {
    extern __shared__ __align__(16) char smem[];

    const int tid = threadIdx.x;
    const int bm = blockIdx.y << 7;
    const int bn = blockIdx.x << 7;
    const uint32_t sbase = smem_u32(smem);

    // loader: 16 chunks of 16B per thread per stage (i<8 -> A, i>=8 -> B)
    const int lrow = tid >> 3;       // 0..15
    const int lc = tid & 7;          // 16B chunk in 128B row
    auto load_stage = [&](int s, int k0) {
        uint32_t st = sbase + s * STAGEB;
#pragma unroll
        for (int i = 0; i < 8; i++) {
            int row = lrow + i * 16;
            cpasync16(st + row * ROWB + lc * 16, A + (size_t)(bm + row) * K + k0 + lc * 8);
        }
#pragma unroll
        for (int i = 0; i < 8; i++) {
            int row = lrow + i * 16;
            cpasync16(st + TILEB + row * ROWB + lc * 16,
                      Bw + (size_t)(bn + row) * K + k0 + lc * 8);
        }
    };

    const int wid = tid >> 5, lane = tid & 31;
    const int wm = wid & 1;          // 2 warps over M: 64 rows each
    const int wn = wid >> 1;         // 2 warps over N: 64 cols each

    float acc[4][8][4];
#pragma unroll
    for (int mt = 0; mt < 4; mt++)
#pragma unroll
        for (int nt = 0; nt < 8; nt++)
#pragma unroll
            for (int r = 0; r < 4; r++) acc[mt][nt][r] = 0.f;

    const int KT = K >> 6;
    load_stage(0, 0);
    cp_commit();

    const uint32_t a_off = (wm * 64 + (lane & 15)) * ROWB + (lane >> 4) * 16;
    const uint32_t b_off = TILEB + (wn * 64 + (lane >> 4) * 8 + (lane & 7)) * ROWB +
                           ((lane >> 3) & 1) * 16;
    const int gb = (bm >> 11) * D;   // gate row for this CTA's batch

    for (int kt = 0; kt < KT; kt++) {
        int s = kt & 1;
        if (kt + 1 < KT) {
            load_stage(s ^ 1, (kt + 1) << 6);
            cp_commit();
            cp_wait<1>();
        } else {
            cp_wait<0>();
        }
        __syncthreads();
        uint32_t st = sbase + s * STAGEB;
#pragma unroll
        for (int kk = 0; kk < 4; kk++) {
            uint32_t a[4][4], b[4][4];
#pragma unroll
            for (int mt = 0; mt < 4; mt++)
                ldmat4(a[mt], st + a_off + mt * 16 * ROWB + kk * 32);
#pragma unroll
            for (int i = 0; i < 4; i++)
                ldmat4(b[i], st + b_off + i * 16 * ROWB + kk * 32);
            if (gate) {
                int kb = gb + (kt << 6) + kk * 16 + (lane & 3) * 2;
                float2 glo = *reinterpret_cast<const float2*>(gate + kb);
                float2 ghi = *reinterpret_cast<const float2*>(gate + kb + 8);
                bf162 glo2 = __floats2bfloat162_rn(glo.x, glo.y);
                bf162 ghi2 = __floats2bfloat162_rn(ghi.x, ghi.y);
#pragma unroll
                for (int mt = 0; mt < 4; mt++) {
                    a[mt][0] = mulbf2(a[mt][0], glo2);
                    a[mt][1] = mulbf2(a[mt][1], glo2);
                    a[mt][2] = mulbf2(a[mt][2], ghi2);
                    a[mt][3] = mulbf2(a[mt][3], ghi2);
                }
            }
#pragma unroll
            for (int mt = 0; mt < 4; mt++)
#pragma unroll
                for (int nt = 0; nt < 8; nt++)
                    mma16816(acc[mt][nt], a[mt], b[nt >> 1][(nt & 1) * 2],
                             b[nt >> 1][(nt & 1) * 2 + 1]);
        }
        __syncthreads();
    }

    // ---- epilogue ----
    const int qrow = lane >> 2;
    const int qcol = (lane & 3) * 2;
#pragma unroll
    for (int nt = 0; nt < 8; nt++) {
        int col = bn + wn * 64 + nt * 8 + qcol;
        float2 bi = *reinterpret_cast<const float2*>(bias + col);
        float2 sc = make_float2(0.f, 0.f);
        if (epi == 2) sc = *reinterpret_cast<const float2*>(scale + col);
#pragma unroll
        for (int mt = 0; mt < 4; mt++) {
#pragma unroll
            for (int half = 0; half < 2; half++) {
                int row = bm + wm * 64 + mt * 16 + qrow + half * 8;
                size_t off = (size_t)row * Nn + col;
                float v0 = acc[mt][nt][half * 2 + 0] + bi.x;
                float v1 = acc[mt][nt][half * 2 + 1] + bi.y;
                if (epi == 0) {
                    bf162 o;
                    o.x = __float2bfloat16(v0);
                    o.y = __float2bfloat16(v1);
                    *reinterpret_cast<bf162*>(Cb + off) = o;
                } else if (epi == 1) {
                    bf162 o;
                    o.x = __float2bfloat16(gelu_exact(v0));
                    o.y = __float2bfloat16(gelu_exact(v1));
                    *reinterpret_cast<bf162*>(Cb + off) = o;
                } else {
                    float2 rv = *reinterpret_cast<const float2*>(res + off);
                    *reinterpret_cast<float2*>(Cf + off) =
                        make_float2(rv.x + v0 * sc.x, rv.y + v1 * sc.y);
                }
            }
        }
        if (epi == 0) {  // column sums (raw acc, bias added later in gate_kernel)
            float cs0 = 0.f, cs1 = 0.f;
#pragma unroll
            for (int mt = 0; mt < 4; mt++) {
                cs0 += acc[mt][nt][0] + acc[mt][nt][2];
                cs1 += acc[mt][nt][1] + acc[mt][nt][3];
            }
#pragma unroll
            for (int o = 4; o <= 16; o <<= 1) {
                cs0 += __shfl_xor_sync(~0u, cs0, o);
                cs1 += __shfl_xor_sync(~0u, cs1, o);
            }
            if (lane < 4) {
                int b = bm >> 11;
                atomicAdd(&g_ct[b * D + col], cs0);
                atomicAdd(&g_ct[b * D + col + 1], cs1);
            }
        }
    }
}

// ------------------------- host launch ---------------------------------------------
extern "C" void kernel_launch(void* const* d_in, const int* in_sizes, int n_in,
                              void* d_out, int out_size) {
    const float* x      = (const float*)d_in[0];
    const float* ln1_g  = (const float*)d_in[1];
    const float* ln1_b  = (const float*)d_in[2];
    const float* w3     = (const float*)d_in[3];
    const float* b3     = (const float*)d_in[4];
    const float* w5     = (const float*)d_in[5];
    const float* b5     = (const float*)d_in[6];
    const float* w7     = (const float*)d_in[7];
    const float* b7     = (const float*)d_in[8];
    const float* wmix   = (const float*)d_in[9];
    const float* bmix   = (const float*)d_in[10];
    const float* cg_w1  = (const float*)d_in[11];
    const float* cg_b1  = (const float*)d_in[12];
    const float* cg_w2  = (const float*)d_in[13];
    const float* cg_b2  = (const float*)d_in[14];
    const float* wout   = (const float*)d_in[15];
    const float* bout   = (const float*)d_in[16];
    const float* ls1    = (const float*)d_in[17];
    const float* ln2_g  = (const float*)d_in[18];
    const float* ln2_b  = (const float*)d_in[19];
    const float* ffn_w1 = (const float*)d_in[20];
    const float* ffn_b1 = (const float*)d_in[21];
    const float* ffn_w2 = (const float*)d_in[22];
    const float* ffn_b2 = (const float*)d_in[23];
    const float* ls2    = (const float*)d_in[24];
    float* out = (float*)d_out;

    void* p;
    cudaGetSymbolAddress(&p, g_h);     bf16* hbuf  = (bf16*)p;
    cudaGetSymbolAddress(&p, g_gm);    bf16* gmbuf = (bf16*)p;
    cudaGetSymbolAddress(&p, g_m2);    bf16* m2buf = (bf16*)p;
    cudaGetSymbolAddress(&p, g_x1);    float* x1buf = (float*)p;
    cudaGetSymbolAddress(&p, g_t);     bf16* tbuf  = (bf16*)p;
    cudaGetSymbolAddress(&p, g_wmixB); bf16* wmixB = (bf16*)p;
    cudaGetSymbolAddress(&p, g_woutT); bf16* woutT = (bf16*)p;
    cudaGetSymbolAddress(&p, g_w1T);   bf16* w1T   = (bf16*)p;
    cudaGetSymbolAddress(&p, g_w2T);   bf16* w2T   = (bf16*)p;
    cudaGetSymbolAddress(&p, g_gate);  float* gate = (float*)p;

    cudaFuncSetAttribute(hgemm_kernel, cudaFuncAttributeMaxDynamicSharedMemorySize, SMEMB);

    // launch order chosen so ncu -s 5 -c 1 profiles gemm1 (index 5)
    taps_kernel<<<1, 512>>>(w3, b3, w5, b5, w7, b7);                        // 0
    ln_kernel<<<NTOK, 128>>>(x, ln1_g, ln1_b, hbuf);                        // 1
    conv_kernel<<<(NTOK * 256) / 256, 256>>>(hbuf, gmbuf);                  // 2
    convert_kernel<<<(D * D) / 256, 256>>>(wmix, wmixB);                    // 3
    zero_ct_kernel<<<(Bsz * D) / 256, 256>>>();                             // 4
    hgemm_kernel<<<dim3(D / 128, NTOK / 128), 128, SMEMB>>>(                // 5 (profiled)
        gmbuf, wmixB, bmix, nullptr, m2buf, NTOK, D, D, 0, nullptr, nullptr, nullptr);
    gate_kernel<<<Bsz, 128>>>(cg_w1, cg_b1, cg_w2, cg_b2, bmix);            // 6
    transconv_kernel<<<dim3(D / 32, D / 32), dim3(32, 8)>>>(wout, woutT, D, D);  // 7
    hgemm_kernel<<<dim3(D / 128, NTOK / 128), 128, SMEMB>>>(                // 8
        m2buf, woutT, bout, x1buf, nullptr, NTOK, D, D, 2, x, ls1, gate);
    ln_kernel<<<NTOK, 128>>>(x1buf, ln2_g, ln2_b, hbuf);                    // 9
    transconv_kernel<<<dim3(HID / 32, D / 32), dim3(32, 8)>>>(ffn_w1, w1T, D, HID);  // 10
    hgemm_kernel<<<dim3(HID / 128, NTOK / 128), 128, SMEMB>>>(              // 11
        hbuf, w1T, ffn_b1, nullptr, tbuf, NTOK, HID, D, 1, nullptr, nullptr, nullptr);
    transconv_kernel<<<dim3(D / 32, HID / 32), dim3(32, 8)>>>(ffn_w2, w2T, HID, D);  // 12
    hgemm_kernel<<<dim3(D / 128, NTOK / 128), 128, SMEMB>>>(                // 13
        tbuf, w2T, ffn_b2, out, nullptr, NTOK, D, HID, 2, x1buf, ls2, nullptr);
}

// round 6
// speedup vs baseline: 1.2285x; 1.0161x over previous
#include <cuda_runtime.h>
#include <cuda_bf16.h>
#include <math.h>
#include <stdint.h>

#define D 512
#define Bsz 16
#define L 2048
#define HID 2048
#define GH 128
#define NTOK (Bsz * L)   // 32768

typedef __nv_bfloat16 bf16;
typedef __nv_bfloat162 bf162;

// ------------------------- scratch (static device globals) -------------------------
__device__ bf16  g_h[(size_t)NTOK * D];    // ln2 out
__device__ bf16  g_gm[(size_t)NTOK * D];   // gelu(conv mix)
__device__ bf16  g_m2[(size_t)NTOK * D];   // mixed2
__device__ float g_x1[(size_t)NTOK * D];   // first residual out
__device__ bf16  g_t[(size_t)NTOK * HID];  // ffn hidden
__device__ bf16  g_wmixB[D * D];
__device__ bf16  g_woutT[D * D];
__device__ bf16  g_w1T[HID * D];
__device__ bf16  g_w2T[D * HID];
__device__ float g_ct[Bsz * D];            // column sums (atomic)
__device__ float g_gate[Bsz * D];

__device__ __forceinline__ float gelu_exact(float v) {
    return 0.5f * v * (1.0f + erff(v * 0.70710678118654752f));
}
__device__ __forceinline__ uint32_t smem_u32(const void* p) {
    uint32_t a;
    asm("{ .reg .u64 t; cvta.to.shared.u64 t, %1; cvt.u32.u64 %0, t; }" : "=r"(a) : "l"(p));
    return a;
}
__device__ __forceinline__ void cpasync16(uint32_t s, const void* g) {
    asm volatile("cp.async.cg.shared.global [%0], [%1], 16;" :: "r"(s), "l"(g));
}
__device__ __forceinline__ void cp_commit() { asm volatile("cp.async.commit_group;"); }
template <int N>
__device__ __forceinline__ void cp_wait() {
    asm volatile("cp.async.wait_group %0;" :: "n"(N));
}
__device__ __forceinline__ void ldmat4(uint32_t* r, uint32_t addr) {
    asm volatile("ldmatrix.sync.aligned.m8n8.x4.shared.b16 {%0,%1,%2,%3}, [%4];"
                 : "=r"(r[0]), "=r"(r[1]), "=r"(r[2]), "=r"(r[3]) : "r"(addr));
}
__device__ __forceinline__ void mma16816(float* c, const uint32_t* a, uint32_t b0,
                                         uint32_t b1) {
    asm volatile(
        "mma.sync.aligned.m16n8k16.row.col.f32.bf16.bf16.f32 "
        "{%0,%1,%2,%3}, {%4,%5,%6,%7}, {%8,%9}, {%0,%1,%2,%3};"
        : "+f"(c[0]), "+f"(c[1]), "+f"(c[2]), "+f"(c[3])
        : "r"(a[0]), "r"(a[1]), "r"(a[2]), "r"(a[3]), "r"(b0), "r"(b1));
}
__device__ __forceinline__ uint32_t mulbf2(uint32_t x, bf162 g) {
    bf162 v = *reinterpret_cast<bf162*>(&x);
    v = __hmul2(v, g);
    return *reinterpret_cast<uint32_t*>(&v);
}

// ------------------------- fused LN1 + 7-tap conv + gelu ---------------------------
// block: 256 thr, handles 32 tokens of one batch; normalizes 38 rows (halo 3) into
// SMEM (bf16), then conv+gelu from SMEM, writes g_gm only.
#define TOKB 32
#define CROWS (TOKB + 6)   // 38
__global__ __launch_bounds__(256) void lnconv_kernel(
    const float* __restrict__ x, const float* __restrict__ g, const float* __restrict__ bb,
    const float* __restrict__ w3, const float* __restrict__ b3,
    const float* __restrict__ w5, const float* __restrict__ b5,
    const float* __restrict__ w7, const float* __restrict__ b7,
    bf16* __restrict__ out) {
    extern __shared__ char sm[];
    float* s_taps = (float*)sm;                       // 512*7 floats
    float* s_cb   = s_taps + 512 * 7;                 // 512 floats
    bf16*  s_rows = (bf16*)(s_cb + 512);              // 38*512 bf16
    float* s_red  = (float*)(s_rows + CROWS * 512);   // 16 floats

    const int tid = threadIdx.x;
    const int b = blockIdx.y;
    const int l0 = blockIdx.x * TOKB;

    // taps + combined bias
    for (int d = tid; d < 512; d += 256) {
        s_cb[d] = (b3[d] + b5[d] + b7[d]) * (1.f / 3.f);
#pragma unroll
        for (int j = 0; j < 7; j++) {
            float tv = w7[d * 7 + j];
            if (j >= 1 && j <= 5) tv += w5[d * 5 + (j - 1)];
            if (j >= 2 && j <= 4) tv += w3[d * 3 + (j - 2)];
            s_taps[d * 7 + j] = tv * (1.f / 3.f);
        }
    }

    const int half = tid >> 7;       // 0/1: two tokens per iteration
    const int ht = tid & 127;
    const int hw = ht >> 5;          // warp within half
    const int lane = tid & 31;

    float4 gg = *reinterpret_cast<const float4*>(g + ht * 4);
    float4 bv = *reinterpret_cast<const float4*>(bb + ht * 4);

    for (int i = half; i < CROWS; i += 2) {  // 19 iters per half (equal counts)
        int l = l0 - 3 + i;
        bool valid = (l >= 0) && (l < L);
        float4 v = make_float4(0.f, 0.f, 0.f, 0.f);
        if (valid)
            v = *reinterpret_cast<const float4*>(x + ((size_t)b * L + l) * D + ht * 4);
        float s = v.x + v.y + v.z + v.w;
#pragma unroll
        for (int o = 16; o; o >>= 1) s += __shfl_xor_sync(~0u, s, o);
        if (lane == 0) s_red[half * 8 + hw] = s;
        __syncthreads();
        float mean = (s_red[half * 8 + 0] + s_red[half * 8 + 1] + s_red[half * 8 + 2] +
                      s_red[half * 8 + 3]) * (1.f / 512.f);
        float dx = v.x - mean, dy = v.y - mean, dz = v.z - mean, dw = v.w - mean;
        float s2 = dx * dx + dy * dy + dz * dz + dw * dw;
#pragma unroll
        for (int o = 16; o; o >>= 1) s2 += __shfl_xor_sync(~0u, s2, o);
        if (lane == 0) s_red[half * 8 + 4 + hw] = s2;
        __syncthreads();
        float rstd = rsqrtf((s_red[half * 8 + 4] + s_red[half * 8 + 5] +
                             s_red[half * 8 + 6] + s_red[half * 8 + 7]) * (1.f / 512.f) +
                            1e-5f);
        bf162 o1, o2;
        if (valid) {
            o1.x = __float2bfloat16(dx * rstd * gg.x + bv.x);
            o1.y = __float2bfloat16(dy * rstd * gg.y + bv.y);
            o2.x = __float2bfloat16(dz * rstd * gg.z + bv.z);
            o2.y = __float2bfloat16(dw * rstd * gg.w + bv.w);
        } else {
            o1.x = o1.y = o2.x = o2.y = __float2bfloat16(0.f);  // zero padding
        }
        uint2 pk;
        pk.x = *reinterpret_cast<uint32_t*>(&o1);
        pk.y = *reinterpret_cast<uint32_t*>(&o2);
        *reinterpret_cast<uint2*>(s_rows + i * 512 + ht * 4) = pk;
        __syncthreads();
    }

    // conv + gelu from SMEM
    for (int it = tid; it < TOKB * 256; it += 256) {
        int ti = it >> 8;
        int dp = (it & 255) * 2;
        float ax = s_cb[dp], ay = s_cb[dp + 1];
#pragma unroll
        for (int j = 0; j < 7; j++) {
            bf162 hv = *reinterpret_cast<const bf162*>(s_rows + (ti + j) * 512 + dp);
            ax = fmaf(__bfloat162float(hv.x), s_taps[dp * 7 + j], ax);
            ay = fmaf(__bfloat162float(hv.y), s_taps[(dp + 1) * 7 + j], ay);
        }
        bf162 o;
        o.x = __float2bfloat16(gelu_exact(ax));
        o.y = __float2bfloat16(gelu_exact(ay));
        *reinterpret_cast<bf162*>(out + ((size_t)b * L + l0 + ti) * D + dp) = o;
    }
}
#define LNCONV_SMEM (512 * 7 * 4 + 512 * 4 + CROWS * 512 * 2 + 16 * 4)

// ------------------------- LayerNorm (fp32 in -> bf16 out), for LN2 -----------------
__global__ void ln_kernel(const float* __restrict__ x, const float* __restrict__ g,
                          const float* __restrict__ bb, bf16* __restrict__ out) {
    int n = blockIdx.x;
    const float* xr = x + (size_t)n * D;
    int t = threadIdx.x;
    float4 v = *reinterpret_cast<const float4*>(xr + t * 4);
    float s = v.x + v.y + v.z + v.w;
    __shared__ float red[4];
#pragma unroll
    for (int o = 16; o; o >>= 1) s += __shfl_xor_sync(~0u, s, o);
    if ((t & 31) == 0) red[t >> 5] = s;
    __syncthreads();
    float mean = (red[0] + red[1] + red[2] + red[3]) * (1.f / 512.f);
    float dx = v.x - mean, dy = v.y - mean, dz = v.z - mean, dw = v.w - mean;
    float s2 = dx * dx + dy * dy + dz * dz + dw * dw;
#pragma unroll
    for (int o = 16; o; o >>= 1) s2 += __shfl_xor_sync(~0u, s2, o);
    __syncthreads();
    if ((t & 31) == 0) red[t >> 5] = s2;
    __syncthreads();
    float rstd = rsqrtf((red[0] + red[1] + red[2] + red[3]) * (1.f / 512.f) + 1e-5f);
    float4 gg = *reinterpret_cast<const float4*>(g + t * 4);
    float4 bbv = *reinterpret_cast<const float4*>(bb + t * 4);
    bf162 o1, o2;
    o1.x = __float2bfloat16(dx * rstd * gg.x + bbv.x);
    o1.y = __float2bfloat16(dy * rstd * gg.y + bbv.y);
    o2.x = __float2bfloat16(dz * rstd * gg.z + bbv.z);
    o2.y = __float2bfloat16(dw * rstd * gg.w + bbv.w);
    uint2 pk;
    pk.x = *reinterpret_cast<uint32_t*>(&o1);
    pk.y = *reinterpret_cast<uint32_t*>(&o2);
    *reinterpret_cast<uint2*>(out + (size_t)n * D + t * 4) = pk;
}

// ------------------------- weight transpose+convert / convert ----------------------
__global__ void transconv_kernel(const float* __restrict__ in, bf16* __restrict__ outp,
                                 int R, int C) {
    __shared__ float tile[32][33];
    int x = blockIdx.x * 32 + threadIdx.x;
    int y = blockIdx.y * 32 + threadIdx.y;
#pragma unroll
    for (int i = 0; i < 32; i += 8)
        tile[threadIdx.y + i][threadIdx.x] = in[(size_t)(y + i) * C + x];
    __syncthreads();
    int ox = blockIdx.y * 32 + threadIdx.x;
    int oy = blockIdx.x * 32 + threadIdx.y;
#pragma unroll
    for (int i = 0; i < 32; i += 8)
        outp[(size_t)(oy + i) * R + ox] = __float2bfloat16(tile[threadIdx.x][threadIdx.y + i]);
}
__global__ void convert_kernel(const float* __restrict__ in, bf16* __restrict__ o) {
    int idx = blockIdx.x * 256 + threadIdx.x;
    o[idx] = __float2bfloat16(in[idx]);
}
__global__ void zero_ct_kernel() {
    g_ct[blockIdx.x * 256 + threadIdx.x] = 0.f;
}

// ------------------------- gate MLP (tiny) ------------------------------------------
__global__ void gate_kernel(const float* __restrict__ cg_w1, const float* __restrict__ cg_b1,
                            const float* __restrict__ cg_w2, const float* __restrict__ cg_b2,
                            const float* __restrict__ bmix) {
    int b = blockIdx.x;
    int t = threadIdx.x;
    __shared__ float ct[D];
    __shared__ float hid[GH];
    for (int d = t; d < D; d += 128)
        ct[d] = g_ct[b * D + d] * (1.f / (float)L) + bmix[d];
    __syncthreads();
    {
        float hv = cg_b1[t];
        for (int d = 0; d < D; d++) hv = fmaf(ct[d], cg_w1[d * GH + t], hv);
        hid[t] = gelu_exact(hv);
    }
    __syncthreads();
    for (int o = t; o < D; o += 128) {
        float s = cg_b2[o];
#pragma unroll 4
        for (int j = 0; j < GH; j++) s = fmaf(hid[j], cg_w2[j * D + o], s);
        g_gate[b * D + o] = 1.f / (1.f + expf(-s));
    }
}

// ------------------------- bf16 MMA GEMM 128x128x64, warp tile 64x64 ---------------
// C = epi(A[M,K] (optionally * gate along K) @ Bw[N,K]^T + bias)
// epi 0: bf16 +bias, accumulate column sums into g_ct (gemm1)
// epi 1: bf16 gelu(+bias)                              (gemm3)
// epi 2: fp32 res + (+bias)*scale                      (gemm2/4)
#define ROWB 144                     // 128B data + 16B pad
#define TILEB (128 * ROWB)           // 18432
#define STAGEB (2 * TILEB)           // A+B per stage
#define SMEMB (2 * STAGEB)           // 73728

__global__ __launch_bounds__(128) void hgemm_kernel(
    const bf16* __restrict__ A, const bf16* __restrict__ Bw,
    const float* __restrict__ bias, float* __restrict__ Cf, bf16* __restrict__ Cb,
    int M, int Nn, int K, int epi, const float* __restrict__ res,
    const float* __restrict__ scale, const float* __restrict__ gate) {
    extern __shared__ __align__(16) char smem[];

    const int tid = threadIdx.x;
    const int bm = blockIdx.y << 7;
    const int bn = blockIdx.x << 7;
    const uint32_t sbase = smem_u32(smem);

    const int lrow = tid >> 3;       // 0..15
    const int lc = tid & 7;          // 16B chunk in 128B row
    auto load_stage = [&](int s, int k0) {
        uint32_t st = sbase + s * STAGEB;
#pragma unroll
        for (int i = 0; i < 8; i++) {
            int row = lrow + i * 16;
            cpasync16(st + row * ROWB + lc * 16, A + (size_t)(bm + row) * K + k0 + lc * 8);
        }
#pragma unroll
        for (int i = 0; i < 8; i++) {
            int row = lrow + i * 16;
            cpasync16(st + TILEB + row * ROWB + lc * 16,
                      Bw + (size_t)(bn + row) * K + k0 + lc * 8);
        }
    };

    const int wid = tid >> 5, lane = tid & 31;
    const int wm = wid & 1;          // 2 warps over M: 64 rows each
    const int wn = wid >> 1;         // 2 warps over N: 64 cols each

    float acc[4][8][4];
#pragma unroll
    for (int mt = 0; mt < 4; mt++)
#pragma unroll
        for (int nt = 0; nt < 8; nt++)
#pragma unroll
            for (int r = 0; r < 4; r++) acc[mt][nt][r] = 0.f;

    const int KT = K >> 6;
    load_stage(0, 0);
    cp_commit();

    const uint32_t a_off = (wm * 64 + (lane & 15)) * ROWB + (lane >> 4) * 16;
    const uint32_t b_off = TILEB + (wn * 64 + (lane >> 4) * 8 + (lane & 7)) * ROWB +
                           ((lane >> 3) & 1) * 16;
    const int gb = (bm >> 11) * D;

    for (int kt = 0; kt < KT; kt++) {
        int s = kt & 1;
        if (kt + 1 < KT) {
            load_stage(s ^ 1, (kt + 1) << 6);
            cp_commit();
            cp_wait<1>();
        } else {
            cp_wait<0>();
        }
        __syncthreads();
        uint32_t st = sbase + s * STAGEB;
#pragma unroll
        for (int kk = 0; kk < 4; kk++) {
            uint32_t a[4][4], b[4][4];
#pragma unroll
            for (int mt = 0; mt < 4; mt++)
                ldmat4(a[mt], st + a_off + mt * 16 * ROWB + kk * 32);
#pragma unroll
            for (int i = 0; i < 4; i++)
                ldmat4(b[i], st + b_off + i * 16 * ROWB + kk * 32);
            if (gate) {
                int kb = gb + (kt << 6) + kk * 16 + (lane & 3) * 2;
                float2 glo = *reinterpret_cast<const float2*>(gate + kb);
                float2 ghi = *reinterpret_cast<const float2*>(gate + kb + 8);
                bf162 glo2 = __floats2bfloat162_rn(glo.x, glo.y);
                bf162 ghi2 = __floats2bfloat162_rn(ghi.x, ghi.y);
#pragma unroll
                for (int mt = 0; mt < 4; mt++) {
                    a[mt][0] = mulbf2(a[mt][0], glo2);
                    a[mt][1] = mulbf2(a[mt][1], glo2);
                    a[mt][2] = mulbf2(a[mt][2], ghi2);
                    a[mt][3] = mulbf2(a[mt][3], ghi2);
                }
            }
#pragma unroll
            for (int mt = 0; mt < 4; mt++)
#pragma unroll
                for (int nt = 0; nt < 8; nt++)
                    mma16816(acc[mt][nt], a[mt], b[nt >> 1][(nt & 1) * 2],
                             b[nt >> 1][(nt & 1) * 2 + 1]);
        }
        __syncthreads();
    }

    // ---- epilogue ----
    const int qrow = lane >> 2;
    const int qcol = (lane & 3) * 2;
#pragma unroll
    for (int nt = 0; nt < 8; nt++) {
        int col = bn + wn * 64 + nt * 8 + qcol;
        float2 bi = *reinterpret_cast<const float2*>(bias + col);
        float2 sc = make_float2(0.f, 0.f);
        if (epi == 2) sc = *reinterpret_cast<const float2*>(scale + col);
#pragma unroll
        for (int mt = 0; mt < 4; mt++) {
#pragma unroll
            for (int half = 0; half < 2; half++) {
                int row = bm + wm * 64 + mt * 16 + qrow + half * 8;
                size_t off = (size_t)row * Nn + col;
                float v0 = acc[mt][nt][half * 2 + 0] + bi.x;
                float v1 = acc[mt][nt][half * 2 + 1] + bi.y;
                if (epi == 0) {
                    bf162 o;
                    o.x = __float2bfloat16(v0);
                    o.y = __float2bfloat16(v1);
                    *reinterpret_cast<bf162*>(Cb + off) = o;
                } else if (epi == 1) {
                    bf162 o;
                    o.x = __float2bfloat16(gelu_exact(v0));
                    o.y = __float2bfloat16(gelu_exact(v1));
                    *reinterpret_cast<bf162*>(Cb + off) = o;
                } else {
                    float2 rv = *reinterpret_cast<const float2*>(res + off);
                    *reinterpret_cast<float2*>(Cf + off) =
                        make_float2(rv.x + v0 * sc.x, rv.y + v1 * sc.y);
                }
            }
        }
        if (epi == 0) {
            float cs0 = 0.f, cs1 = 0.f;
#pragma unroll
            for (int mt = 0; mt < 4; mt++) {
                cs0 += acc[mt][nt][0] + acc[mt][nt][2];
                cs1 += acc[mt][nt][1] + acc[mt][nt][3];
            }
#pragma unroll
            for (int o = 4; o <= 16; o <<= 1) {
                cs0 += __shfl_xor_sync(~0u, cs0, o);
                cs1 += __shfl_xor_sync(~0u, cs1, o);
            }
            if (lane < 4) {
                int b = bm >> 11;
                atomicAdd(&g_ct[b * D + col], cs0);
                atomicAdd(&g_ct[b * D + col + 1], cs1);
            }
        }
    }
}

// ------------------------- host launch ---------------------------------------------
extern "C" void kernel_launch(void* const* d_in, const int* in_sizes, int n_in,
                              void* d_out, int out_size) {
    const float* x      = (const float*)d_in[0];
    const float* ln1_g  = (const float*)d_in[1];
    const float* ln1_b  = (const float*)d_in[2];
    const float* w3     = (const float*)d_in[3];
    const float* b3     = (const float*)d_in[4];
    const float* w5     = (const float*)d_in[5];
    const float* b5     = (const float*)d_in[6];
    const float* w7     = (const float*)d_in[7];
    const float* b7     = (const float*)d_in[8];
    const float* wmix   = (const float*)d_in[9];
    const float* bmix   = (const float*)d_in[10];
    const float* cg_w1  = (const float*)d_in[11];
    const float* cg_b1  = (const float*)d_in[12];
    const float* cg_w2  = (const float*)d_in[13];
    const float* cg_b2  = (const float*)d_in[14];
    const float* wout   = (const float*)d_in[15];
    const float* bout   = (const float*)d_in[16];
    const float* ls1    = (const float*)d_in[17];
    const float* ln2_g  = (const float*)d_in[18];
    const float* ln2_b  = (const float*)d_in[19];
    const float* ffn_w1 = (const float*)d_in[20];
    const float* ffn_b1 = (const float*)d_in[21];
    const float* ffn_w2 = (const float*)d_in[22];
    const float* ffn_b2 = (const float*)d_in[23];
    const float* ls2    = (const float*)d_in[24];
    float* out = (float*)d_out;

    void* p;
    cudaGetSymbolAddress(&p, g_h);     bf16* hbuf  = (bf16*)p;
    cudaGetSymbolAddress(&p, g_gm);    bf16* gmbuf = (bf16*)p;
    cudaGetSymbolAddress(&p, g_m2);    bf16* m2buf = (bf16*)p;
    cudaGetSymbolAddress(&p, g_x1);    float* x1buf = (float*)p;
    cudaGetSymbolAddress(&p, g_t);     bf16* tbuf  = (bf16*)p;
    cudaGetSymbolAddress(&p, g_wmixB); bf16* wmixB = (bf16*)p;
    cudaGetSymbolAddress(&p, g_woutT); bf16* woutT = (bf16*)p;
    cudaGetSymbolAddress(&p, g_w1T);   bf16* w1T   = (bf16*)p;
    cudaGetSymbolAddress(&p, g_w2T);   bf16* w2T   = (bf16*)p;
    cudaGetSymbolAddress(&p, g_gate);  float* gate = (float*)p;

    cudaFuncSetAttribute(hgemm_kernel, cudaFuncAttributeMaxDynamicSharedMemorySize, SMEMB);
    cudaFuncSetAttribute(lnconv_kernel, cudaFuncAttributeMaxDynamicSharedMemorySize,
                         LNCONV_SMEM);

    // launch order: gemm1 at index 3 (ncu captures launch index 3)
    convert_kernel<<<(D * D) / 256, 256>>>(wmix, wmixB);                    // 0
    lnconv_kernel<<<dim3(L / TOKB, Bsz), 256, LNCONV_SMEM>>>(               // 1
        x, ln1_g, ln1_b, w3, b3, w5, b5, w7, b7, gmbuf);
    zero_ct_kernel<<<(Bsz * D) / 256, 256>>>();                             // 2
    hgemm_kernel<<<dim3(D / 128, NTOK / 128), 128, SMEMB>>>(                // 3 (profiled)
        gmbuf, wmixB, bmix, nullptr, m2buf, NTOK, D, D, 0, nullptr, nullptr, nullptr);
    gate_kernel<<<Bsz, 128>>>(cg_w1, cg_b1, cg_w2, cg_b2, bmix);            // 4
    transconv_kernel<<<dim3(D / 32, D / 32), dim3(32, 8)>>>(wout, woutT, D, D);  // 5
    hgemm_kernel<<<dim3(D / 128, NTOK / 128), 128, SMEMB>>>(                // 6
        m2buf, woutT, bout, x1buf, nullptr, NTOK, D, D, 2, x, ls1, gate);
    ln_kernel<<<NTOK, 128>>>(x1buf, ln2_g, ln2_b, hbuf);                    // 7
    transconv_kernel<<<dim3(HID / 32, D / 32), dim3(32, 8)>>>(ffn_w1, w1T, D, HID);  // 8
    hgemm_kernel<<<dim3(HID / 128, NTOK / 128), 128, SMEMB>>>(              // 9
        hbuf, w1T, ffn_b1, nullptr, tbuf, NTOK, HID, D, 1, nullptr, nullptr, nullptr);
    transconv_kernel<<<dim3(D / 32, HID / 32), dim3(32, 8)>>>(ffn_w2, w2T, HID, D);  // 10
    hgemm_kernel<<<dim3(D / 128, NTOK / 128), 128, SMEMB>>>(                // 11
        tbuf, w2T, ffn_b2, out, nullptr, NTOK, D, HID, 2, x1buf, ls2, nullptr);
}